// round 16
// baseline (speedup 1.0000x reference)
#include <cuda_runtime.h>
#include <math.h>

// Problem constants (fixed by the reference)
#define B_FRAMES 256
#define N_COLS   576
#define MR_ROWS  144
#define Z_LIFT   24
#define N_IT     3
#define ROW_DEG  15
#define N_MSG    (MR_ROWS * ROW_DEG)   // 2160
#define NB_A     ((MR_ROWS / Z_LIFT) * (N_COLS / Z_LIFT) * N_IT)  // 432
#define NCHUNK   (N_COLS / 32)         // 18 column chunks per row

#define BT    256                      // threads per CTA (1 frame/CTA)
#define GRID  B_FRAMES                 // 256 CTAs, 2/SM -> ALL co-resident
#define NPASS (MR_ROWS / 16)           // 9 row passes (16-lane groups)
#define QMAX  16                       // padded column depth (max col degree < 16)
#define CB_J  5                        // ceil(144/32) row rounds per column

#define NPROD_A 18                     // phase-A producer CTAs
#define NPROD_B 72                     // phase-B producer CTAs

// Graph scratch (rebuilt from H each launch; identical content every launch)
__device__ unsigned g_row_mask[MR_ROWS][NCHUNK];
__device__ unsigned char g_row_pref8[MR_ROWS][NCHUNK];
// Per-edge packed info, e = m*15+slot:
//   bits[0:10)=c  [10:14)=q(col rank)  [14:17)=m/24  [17:22)=c/24
__device__ int g_einfo[N_MSG];

// Monotonic counters (never reset; replay-safe by construction).
__device__ unsigned long long g_entry;  // +256 per launch (1 per CTA)
__device__ unsigned long long g_barA;   // +18 per launch (phase-A producers)
__device__ unsigned long long g_barB;   // +72 per launch (phase-B producers)

__device__ __forceinline__ void wait_counter(unsigned long long* ctr,
                                             unsigned long long target) {
    // tid 0 polls; whole CTA releases via the following __syncthreads().
    if (threadIdx.x == 0) {
        while (*(volatile unsigned long long*)ctr < target) __nanosleep(32);
        __threadfence();
    }
    __syncthreads();
}

// ---------------------------------------------------------------------------
// Single kernel: [stage + phase A (18 CTAs)] -> waitA -> [phase B (72 CTAs)]
// -> waitB -> [decode]. Consumers never atomically touch the counters: the
// launch index comes from a per-CTA entry ticket whose latency hides behind
// shared-memory staging.
// ---------------------------------------------------------------------------
__global__ __launch_bounds__(BT, 2) void nms_fused(
    const int*   __restrict__ H,
    const float* __restrict__ r,
    const float* __restrict__ alpha,
    const float* __restrict__ beta,
    float* __restrict__ out)
{
    __shared__ float s_Ecol[QMAX * N_COLS];   // 36864 B column-major, zero-padded
    __shared__ float s_r[N_COLS];
    __shared__ float s_sumE[N_COLS];
    __shared__ float s_a[NB_A];
    __shared__ float s_b[NB_A];
    __shared__ unsigned long long s_ticket;

    const int tid    = threadIdx.x;        // 0..255
    const int b      = blockIdx.x;
    const int wid    = tid >> 5;
    const int lane   = tid & 31;
    const int grp    = tid >> 4;           // 16-lane row group (0..15)
    const int k      = tid & 15;           // edge slot (15 = padding)
    const bool act   = (k < ROW_DEG);
    const unsigned hmask = 0xFFFFu << (tid & 16);

    // Entry ticket FIRST: its ~300cyc latency hides behind the staging below.
    if (tid == 0) s_ticket = atomicAdd(&g_entry, 1ULL);

    // ---- stage frame inputs (independent of graph structure) ----
    for (int i = tid; i < NB_A; i += BT) { s_a[i] = alpha[i]; s_b[i] = beta[i]; }
    for (int i = tid; i < N_COLS; i += BT) s_r[i] = r[b * N_COLS + i];
    {
        float4* z = (float4*)s_Ecol;
        #pragma unroll
        for (int i = 0; i < (QMAX * N_COLS) / 4 / BT; ++i)
            z[tid + i * BT] = make_float4(0.f, 0.f, 0.f, 0.f);
    }

    // ---- phase A: row bitmasks + prefix (CTAs 0..17, one warp per row) ----
    if (b < NPROD_A) {
        const int row = b * 8 + wid;       // 18 CTAs x 8 warps = 144 rows
        const int* hr = H + row * N_COLS;
        int vals[NCHUNK];
        #pragma unroll
        for (int j = 0; j < NCHUNK; ++j) vals[j] = hr[j * 32 + lane];
        int cnt = 0;
        #pragma unroll
        for (int j = 0; j < NCHUNK; ++j) {
            unsigned ball = __ballot_sync(0xffffffffu, vals[j] != 0);
            if (lane == 0) {
                g_row_mask[row][j]  = ball;
                g_row_pref8[row][j] = (unsigned char)cnt;
            }
            cnt += __popc(ball);
        }
        if (lane == 0) __threadfence();    // writer publishes its masks/pref
    }
    __syncthreads();                       // ticket + staging + phase A visible
    const unsigned long long launch = s_ticket >> 8;   // /GRID (=256)
    if (b < NPROD_A && tid == 0) atomicAdd(&g_barA, 1ULL);

    // ---- phase B: per-edge packed info (CTAs 0..71, one warp per column) ----
    if (b < NPROD_B) {
        wait_counter(&g_barA, (launch + 1ULL) * NPROD_A);
        const int c = b * 8 + wid;         // 72 CTAs x 8 warps = 576 columns
        const int cw = c >> 5, cb = c & 31;
        const unsigned colbelow  = (1u << cb) - 1u;
        const unsigned lanebelow = (1u << lane) - 1u;
        unsigned mask[CB_J];
        unsigned char pref[CB_J];
        #pragma unroll
        for (int j = 0; j < CB_J; ++j) {
            int m = j * 32 + lane;
            if (m < MR_ROWS) { mask[j] = g_row_mask[m][cw]; pref[j] = g_row_pref8[m][cw]; }
            else             { mask[j] = 0u; pref[j] = 0; }
        }
        int cnt = 0;
        #pragma unroll
        for (int j = 0; j < CB_J; ++j) {
            const int m = j * 32 + lane;
            const bool hit = (m < MR_ROWS) && ((mask[j] >> cb) & 1u);
            unsigned ball = __ballot_sync(0xffffffffu, hit);
            int before = __popc(ball & lanebelow);
            if (hit) {
                int slot = (int)pref[j] + __popc(mask[j] & colbelow);
                int q = cnt + before;
                g_einfo[m * ROW_DEG + slot] =
                    c | (q << 10) | ((m / Z_LIFT) << 14) | ((c / Z_LIFT) << 17);
            }
            cnt += __popc(ball);
        }
        __threadfence();                   // every einfo writer publishes
        __syncthreads();
        if (tid == 0) atomicAdd(&g_barB, 1ULL);
    }

    // ---- wait for einfo, then decode this CTA's frame ----
    wait_counter(&g_barB, (launch + 1ULL) * NPROD_B);

    int ew[NPASS];
    #pragma unroll
    for (int p = 0; p < NPASS; ++p) {
        int e = (p * 16 + grp) * ROW_DEG + (act ? k : 0);
        ew[p] = g_einfo[e];                // L2-hot, batched MLP 9
    }
    int   cc[NPASS], wpos[NPASS], aoff[NPASS];
    float rv[NPASS], Ep[NPASS];
    #pragma unroll
    for (int p = 0; p < NPASS; ++p) {
        int w = act ? ew[p] : 0;
        cc[p]   = w & 1023;
        wpos[p] = ((w >> 10) & 15) * N_COLS + cc[p];
        aoff[p] = ((w >> 14) & 7) * ((N_COLS / Z_LIFT) * N_IT)
                + ((w >> 17) & 31) * N_IT;
        Ep[p]   = 0.0f;
    }
    #pragma unroll
    for (int p = 0; p < NPASS; ++p) rv[p] = s_r[cc[p]];

    for (int it = 0; it < N_IT; ++it) {
        float v[NPASS];
        if (it == 0) {
            #pragma unroll
            for (int p = 0; p < NPASS; ++p) v[p] = rv[p];
        } else {
            #pragma unroll
            for (int p = 0; p < NPASS; ++p)
                v[p] = rv[p] + s_sumE[cc[p]] - Ep[p];
        }

        #pragma unroll
        for (int p = 0; p < NPASS; ++p) {
            float av = act ? fabsf(v[p]) : INFINITY;

            unsigned negb = __ballot_sync(0xffffffffu, act && (v[p] < 0.0f));
            int parity = __popc(negb & hmask) & 1;

            float m1 = av;
            #pragma unroll
            for (int d = 1; d < 16; d <<= 1)
                m1 = fminf(m1, __shfl_xor_sync(0xffffffffu, m1, d, 16));
            unsigned bm = __ballot_sync(0xffffffffu, av == m1) & hmask;
            const bool isl = ((tid & 31) == (__ffs(bm) - 1));  // first argmin
            float m2 = isl ? INFINITY : av;
            #pragma unroll
            for (int d = 1; d < 16; d <<= 1)
                m2 = fminf(m2, __shfl_xor_sync(0xffffffffu, m2, d, 16));

            if (act) {
                int   ai  = aoff[p] + it;
                float sel = isl ? m2 : m1;
                float mag = fmaxf(sel - s_b[ai], 0.0f);
                float E = s_a[ai] * mag;
                int neg = parity ^ ((v[p] < 0.0f) ? 1 : 0);
                E = neg ? -E : E;
                E = (m1 == 0.0f) ? 0.0f : E;     // zero in row -> whole row E=0
                Ep[p] = E;
                s_Ecol[wpos[p]] = E;
            }
        }
        __syncthreads();

        if (it < N_IT - 1) {
            for (int c = tid; c < N_COLS; c += BT) {
                float x[QMAX];
                #pragma unroll
                for (int q = 0; q < QMAX; ++q) x[q] = s_Ecol[q * N_COLS + c];
                float s = ((x[0]+x[1])+(x[2]+x[3])) + ((x[4]+x[5])+(x[6]+x[7]))
                        + (((x[8]+x[9])+(x[10]+x[11])) + ((x[12]+x[13])+(x[14]+x[15])));
                s_sumE[c] = s;
            }
            __syncthreads();
        } else {
            for (int c = tid; c < N_COLS; c += BT) {
                float x[QMAX];
                #pragma unroll
                for (int q = 0; q < QMAX; ++q) x[q] = s_Ecol[q * N_COLS + c];
                float s = ((x[0]+x[1])+(x[2]+x[3])) + ((x[4]+x[5])+(x[6]+x[7]))
                        + (((x[8]+x[9])+(x[10]+x[11])) + ((x[12]+x[13])+(x[14]+x[15])));
                out[b * N_COLS + c] = s_r[c] + s;
            }
        }
    }
}

extern "C" void kernel_launch(void* const* d_in, const int* in_sizes, int n_in,
                              void* d_out, int out_size) {
    const int*   H     = (const int*)d_in[3];     // (144, 576)
    const float* r     = (const float*)d_in[0];   // (256, 576)
    const float* alpha = (const float*)d_in[1];   // (6, 24, 3)
    const float* beta  = (const float*)d_in[2];   // (6, 24, 3)
    float* out = (float*)d_out;                   // (256, 576)

    nms_fused<<<GRID, BT>>>(H, r, alpha, beta, out);
}

// round 17
// speedup vs baseline: 1.5280x; 1.5280x over previous
#include <cuda_runtime.h>
#include <math.h>

// Problem constants (fixed by the reference)
#define B_FRAMES 256
#define N_COLS   576
#define MR_ROWS  144
#define Z_LIFT   24
#define N_IT     3
#define ROW_DEG  15
#define N_MSG    (MR_ROWS * ROW_DEG)   // 2160
#define NB_A     ((MR_ROWS / Z_LIFT) * (N_COLS / Z_LIFT) * N_IT)  // 432
#define NCHUNK   (N_COLS / 32)         // 18 column chunks per row

#define BT    256                      // threads per CTA (1 frame/CTA)
#define GRID  B_FRAMES                 // 256 CTAs, 2/SM -> ALL co-resident
#define QMAX  16                       // padded column depth (max col degree < 16)
#define CB_J  5                        // ceil(144/32) row rounds per column

// Graph scratch (rebuilt from H each launch; identical content every launch)
__device__ unsigned g_row_mask[MR_ROWS][NCHUNK];
__device__ unsigned char g_row_pref8[MR_ROWS][NCHUNK];
// Per-edge packed info, e = m*15+slot:
//   bits[0:10)=c  [10:14)=q(col rank)  [14:17)=m/24  [17:22)=c/24
__device__ int g_einfo[N_MSG];

// Monotonic grid-barrier counter (never reset; replay-safe).
__device__ unsigned long long g_bar;

__device__ __forceinline__ void grid_barrier() {
    __syncthreads();
    if (threadIdx.x == 0) {
        __threadfence();
        unsigned long long old = atomicAdd(&g_bar, 1ULL);
        unsigned long long target = (old / GRID + 1ULL) * GRID;
        while (*(volatile unsigned long long*)&g_bar < target) __nanosleep(64);
        __threadfence();
    }
    __syncthreads();
}

// ---------------------------------------------------------------------------
// Single fused kernel: [stage + phase A] -> gbar -> [phase B] -> gbar ->
// [decode: thread-per-row CN (pure ALU, no warp collectives) + q-slab gather].
// ---------------------------------------------------------------------------
__global__ __launch_bounds__(BT, 2) void nms_fused(
    const int*   __restrict__ H,
    const float* __restrict__ r,
    const float* __restrict__ alpha,
    const float* __restrict__ beta,
    float* __restrict__ out)
{
    __shared__ float s_Ecol[QMAX * N_COLS];   // 36864 B column-major, zero-padded
    __shared__ float s_r[N_COLS];
    __shared__ float s_sumE[N_COLS];
    __shared__ float s_a[NB_A];
    __shared__ float s_b[NB_A];

    const int tid  = threadIdx.x;          // 0..255
    const int b    = blockIdx.x;
    const int wid  = tid >> 5;
    const int lane = tid & 31;

    // ---- stage frame inputs ----
    for (int i = tid; i < NB_A; i += BT) { s_a[i] = alpha[i]; s_b[i] = beta[i]; }
    for (int i = tid; i < N_COLS; i += BT) s_r[i] = r[b * N_COLS + i];
    {
        float4* z = (float4*)s_Ecol;
        #pragma unroll
        for (int i = 0; i < (QMAX * N_COLS) / 4 / BT; ++i)
            z[tid + i * BT] = make_float4(0.f, 0.f, 0.f, 0.f);
    }

    // ---- phase A: row bitmasks + prefix (CTAs 0..17, one warp per row) ----
    if (b < 18) {
        const int row = b * 8 + wid;       // 18 CTAs x 8 warps = 144 rows
        const int* hr = H + row * N_COLS;
        int vals[NCHUNK];
        #pragma unroll
        for (int j = 0; j < NCHUNK; ++j) vals[j] = hr[j * 32 + lane];
        int cnt = 0;
        #pragma unroll
        for (int j = 0; j < NCHUNK; ++j) {
            unsigned ball = __ballot_sync(0xffffffffu, vals[j] != 0);
            if (lane == 0) {
                g_row_mask[row][j]  = ball;
                g_row_pref8[row][j] = (unsigned char)cnt;
            }
            cnt += __popc(ball);
        }
    }
    grid_barrier();

    // ---- phase B: per-edge packed info (CTAs 0..71, one warp per column) ----
    if (b < 72) {
        const int c = b * 8 + wid;         // 72 CTAs x 8 warps = 576 columns
        const int cw = c >> 5, cb = c & 31;
        const unsigned colbelow  = (1u << cb) - 1u;
        const unsigned lanebelow = (1u << lane) - 1u;
        unsigned mask[CB_J];
        unsigned char pref[CB_J];
        #pragma unroll
        for (int j = 0; j < CB_J; ++j) {
            int m = j * 32 + lane;
            if (m < MR_ROWS) { mask[j] = g_row_mask[m][cw]; pref[j] = g_row_pref8[m][cw]; }
            else             { mask[j] = 0u; pref[j] = 0; }
        }
        int cnt = 0;
        #pragma unroll
        for (int j = 0; j < CB_J; ++j) {
            const int m = j * 32 + lane;
            const bool hit = (m < MR_ROWS) && ((mask[j] >> cb) & 1u);
            unsigned ball = __ballot_sync(0xffffffffu, hit);
            int before = __popc(ball & lanebelow);
            if (hit) {
                int slot = (int)pref[j] + __popc(mask[j] & colbelow);
                int q = cnt + before;
                g_einfo[m * ROW_DEG + slot] =
                    c | (q << 10) | ((m / Z_LIFT) << 14) | ((c / Z_LIFT) << 17);
            }
            cnt += __popc(ball);
        }
    }
    grid_barrier();

    // ---- decode: thread tid < 144 owns check row tid (all 15 edges) ----
    const bool cn = (tid < MR_ROWS);
    int   cIdx[ROW_DEG], wIdx[ROW_DEG], aoff[ROW_DEG];
    float rv[ROW_DEG], E[ROW_DEG];
    if (cn) {
        #pragma unroll
        for (int k = 0; k < ROW_DEG; ++k) {
            int w = g_einfo[tid * ROW_DEG + k];        // batched, L2-hot
            cIdx[k] = w & 1023;
            wIdx[k] = ((w >> 10) & 15) * N_COLS + cIdx[k];
            aoff[k] = ((w >> 14) & 7) * ((N_COLS / Z_LIFT) * N_IT)
                    + ((w >> 17) & 31) * N_IT;
            E[k]    = 0.0f;
        }
        #pragma unroll
        for (int k = 0; k < ROW_DEG; ++k) rv[k] = s_r[cIdx[k]];
    }

    for (int it = 0; it < N_IT; ++it) {
        if (cn) {
            // v->c messages (batched LDS, MLP 15)
            float v[ROW_DEG], av[ROW_DEG];
            if (it == 0) {
                #pragma unroll
                for (int k = 0; k < ROW_DEG; ++k) v[k] = rv[k];
            } else {
                #pragma unroll
                for (int k = 0; k < ROW_DEG; ++k)
                    v[k] = rv[k] + s_sumE[cIdx[k]] - E[k];
            }
            #pragma unroll
            for (int k = 0; k < ROW_DEG; ++k) av[k] = fabsf(v[k]);

            // row sign parity: XOR of all sign bits
            int sx = 0;
            #pragma unroll
            for (int k = 0; k < ROW_DEG; ++k) sx ^= __float_as_int(v[k]);
            const unsigned px = (unsigned)sx & 0x80000000u;

            // (min1, min2) multiset merge tree, depth 4 (pure FMNMX, no chains)
            float p1[8], p2[8];
            #pragma unroll
            for (int i = 0; i < 7; ++i) {
                p1[i] = fminf(av[2 * i], av[2 * i + 1]);
                p2[i] = fmaxf(av[2 * i], av[2 * i + 1]);
            }
            p1[7] = av[14]; p2[7] = INFINITY;
            #pragma unroll
            for (int s = 4; s >= 1; s >>= 1) {
                #pragma unroll
                for (int i = 0; i < 4; ++i) {
                    if (i < s) {
                        float n1 = fminf(p1[i], p1[i + s]);
                        float n2 = fminf(fmaxf(p1[i], p1[i + s]),
                                         fminf(p2[i], p2[i + s]));
                        p1[i] = n1; p2[i] = n2;
                    }
                }
            }
            const float m1 = p1[0], m2 = p2[0];

            // first argmin index (value-equivalent tie-break vs reference)
            unsigned em = 0u;
            #pragma unroll
            for (int k = 0; k < ROW_DEG; ++k)
                em |= (av[k] == m1) ? (1u << k) : 0u;
            const int kmin = __ffs(em) - 1;
            const bool live = (m1 != 0.0f);            // any zero -> row E = 0

            // extrinsic outputs
            #pragma unroll
            for (int k = 0; k < ROW_DEG; ++k) {
                int   ai  = aoff[k] + it;
                float sel = (k == kmin) ? m2 : m1;
                float mag = fmaxf(sel - s_b[ai], 0.0f);
                float Ea  = s_a[ai] * mag;
                unsigned sb = (px ^ (unsigned)__float_as_int(v[k])) & 0x80000000u;
                float Ek = __int_as_float(__float_as_int(Ea) ^ (int)sb);
                Ek = live ? Ek : 0.0f;
                E[k] = Ek;
                s_Ecol[wIdx[k]] = Ek;
            }
        }
        __syncthreads();

        // ---- column sums: 16 conflict-free LDS + tree add per column ----
        if (it < N_IT - 1) {
            for (int c = tid; c < N_COLS; c += BT) {
                float x[QMAX];
                #pragma unroll
                for (int q = 0; q < QMAX; ++q) x[q] = s_Ecol[q * N_COLS + c];
                float s = ((x[0]+x[1])+(x[2]+x[3])) + ((x[4]+x[5])+(x[6]+x[7]))
                        + (((x[8]+x[9])+(x[10]+x[11])) + ((x[12]+x[13])+(x[14]+x[15])));
                s_sumE[c] = s;
            }
            __syncthreads();
        } else {
            // fused epilogue: posterior LLRs straight to GMEM
            for (int c = tid; c < N_COLS; c += BT) {
                float x[QMAX];
                #pragma unroll
                for (int q = 0; q < QMAX; ++q) x[q] = s_Ecol[q * N_COLS + c];
                float s = ((x[0]+x[1])+(x[2]+x[3])) + ((x[4]+x[5])+(x[6]+x[7]))
                        + (((x[8]+x[9])+(x[10]+x[11])) + ((x[12]+x[13])+(x[14]+x[15])));
                out[b * N_COLS + c] = s_r[c] + s;
            }
        }
    }
}

extern "C" void kernel_launch(void* const* d_in, const int* in_sizes, int n_in,
                              void* d_out, int out_size) {
    const int*   H     = (const int*)d_in[3];     // (144, 576)
    const float* r     = (const float*)d_in[0];   // (256, 576)
    const float* alpha = (const float*)d_in[1];   // (6, 24, 3)
    const float* beta  = (const float*)d_in[2];   // (6, 24, 3)
    float* out = (float*)d_out;                   // (256, 576)

    nms_fused<<<GRID, BT>>>(H, r, alpha, beta, out);
}